// round 2
// baseline (speedup 1.0000x reference)
#include <cuda_runtime.h>
#include <cuda_bf16.h>
#include <cstdint>

// Single-query attention, B=4096, T=1024, D=64.
//   attn = softmax(mask_fill(q·k^T / 8, pad_mask, -1000))
//   out  = attn @ v
// Outputs: out [B,64] then (if out_size allows) attn [B,1024], concatenated.
//
// Memory-bound: streams K (1GiB) + V (1GiB) exactly once, fully coalesced
// float4 loads. One 256-thread CTA per batch row.
//
// pad_mask arrives as a 4-byte dtype (harness supports float32/int32/bf16
// only; jnp.bool_ is widened). Reading as int with a !=0 test is correct for
// both int32 {0,1} and float32 {0.0f,1.0f} encodings.

namespace {

constexpr int T_DIM = 1024;
constexpr int D_DIM = 64;
constexpr float INV_TEMP = 0.125f;   // 1/8
constexpr float MASK_FILL = -1000.0f;

__global__ __launch_bounds__(256, 8)
void sdpa_kernel(const float* __restrict__ q,
                 const float* __restrict__ k,
                 const float* __restrict__ v,
                 const int* __restrict__ mask,
                 float* __restrict__ out,
                 float* __restrict__ attn_out)
{
    const int b    = blockIdx.x;
    const int tid  = threadIdx.x;            // 0..255
    const int warp = tid >> 5;               // 0..7
    const int lane = tid & 31;

    __shared__ float4 qs4[D_DIM / 4];        // 16 float4 = q row
    __shared__ float  sc[T_DIM];             // scores -> probs (4 KB)
    __shared__ float  red_max[8];
    __shared__ float  red_sum[8];
    __shared__ float  outp[8][D_DIM];        // per-warp output partials (2 KB)

    // ---- load q row into shared ----
    if (tid < D_DIM / 4) {
        qs4[tid] = reinterpret_cast<const float4*>(q + (size_t)b * D_DIM)[tid];
    }
    __syncthreads();

    const float4* __restrict__ k4 =
        reinterpret_cast<const float4*>(k + (size_t)b * T_DIM * D_DIM);
    const float4* __restrict__ v4 =
        reinterpret_cast<const float4*>(v + (size_t)b * T_DIM * D_DIM);
    const int* __restrict__ mrow = mask + (size_t)b * T_DIM;

    // Warp layout for row streaming: 16 lanes per row, 2 rows per warp-iter.
    const int half = lane >> 4;              // 0 or 1: which row of the pair
    const int qi   = lane & 15;              // which float4 within the row
    const float4 qv = qs4[qi];

    // ---- phase 1: scores s[t] = (k[t]·q)/8, masked ----
    #pragma unroll 4
    for (int t0 = warp * 2; t0 < T_DIM; t0 += 16) {
        const int t = t0 + half;
        const float4 kv = k4[t * (D_DIM / 4) + qi];
        float p = kv.x * qv.x + kv.y * qv.y + kv.z * qv.z + kv.w * qv.w;
        // reduce across the 16 lanes of this row
        p += __shfl_xor_sync(0xffffffffu, p, 1);
        p += __shfl_xor_sync(0xffffffffu, p, 2);
        p += __shfl_xor_sync(0xffffffffu, p, 4);
        p += __shfl_xor_sync(0xffffffffu, p, 8);
        if (qi == 0) {
            float s = p * INV_TEMP;
            if (mrow[t] != 0) s = MASK_FILL;
            sc[t] = s;
        }
    }
    __syncthreads();

    // ---- phase 2: softmax over T ----
    float mx = -1e30f;
    #pragma unroll
    for (int t = tid; t < T_DIM; t += 256) mx = fmaxf(mx, sc[t]);
    #pragma unroll
    for (int o = 16; o > 0; o >>= 1)
        mx = fmaxf(mx, __shfl_xor_sync(0xffffffffu, mx, o));
    if (lane == 0) red_max[warp] = mx;
    __syncthreads();

    float bm = red_max[0];
    #pragma unroll
    for (int i = 1; i < 8; i++) bm = fmaxf(bm, red_max[i]);

    float psum = 0.0f;
    #pragma unroll
    for (int t = tid; t < T_DIM; t += 256) {
        const float e = __expf(sc[t] - bm);
        sc[t] = e;
        psum += e;
    }
    #pragma unroll
    for (int o = 16; o > 0; o >>= 1)
        psum += __shfl_xor_sync(0xffffffffu, psum, o);
    if (lane == 0) red_sum[warp] = psum;
    __syncthreads();

    float tot = red_sum[0];
    #pragma unroll
    for (int i = 1; i < 8; i++) tot += red_sum[i];
    const float inv = 1.0f / tot;

    // normalize in shared; emit attn output (coalesced)
    #pragma unroll
    for (int t = tid; t < T_DIM; t += 256) {
        const float pnorm = sc[t] * inv;
        sc[t] = pnorm;
        if (attn_out) attn_out[(size_t)b * T_DIM + t] = pnorm;
    }
    __syncthreads();

    // ---- phase 3: out[d] = sum_t p[t] * v[t,d] ----
    float4 acc = make_float4(0.f, 0.f, 0.f, 0.f);
    #pragma unroll 4
    for (int t0 = warp * 2; t0 < T_DIM; t0 += 16) {
        const int t = t0 + half;
        const float p = sc[t];                       // broadcast within half-warp
        const float4 vv = v4[t * (D_DIM / 4) + qi];
        acc.x += p * vv.x;
        acc.y += p * vv.y;
        acc.z += p * vv.z;
        acc.w += p * vv.w;
    }
    // combine the two halves (lane l with lane l^16, same qi)
    acc.x += __shfl_xor_sync(0xffffffffu, acc.x, 16);
    acc.y += __shfl_xor_sync(0xffffffffu, acc.y, 16);
    acc.z += __shfl_xor_sync(0xffffffffu, acc.z, 16);
    acc.w += __shfl_xor_sync(0xffffffffu, acc.w, 16);
    if (half == 0) {
        reinterpret_cast<float4*>(outp[warp])[qi] = acc;
    }
    __syncthreads();

    if (tid < D_DIM) {
        float s = 0.0f;
        #pragma unroll
        for (int w = 0; w < 8; w++) s += outp[w][tid];
        out[(size_t)b * D_DIM + tid] = s;
    }
}

} // namespace

extern "C" void kernel_launch(void* const* d_in, const int* in_sizes, int n_in,
                              void* d_out, int out_size)
{
    const float* q = (const float*)d_in[0];             // [B,64]
    const float* k = (const float*)d_in[1];             // [B,1024,64]
    const float* v = (const float*)d_in[2];             // [B,1024,64]
    const int*   mask = (const int*)d_in[3];            // [B,1024] bool->i32/f32

    const int B = in_sizes[0] / D_DIM;                  // 4096

    float* out = (float*)d_out;                         // [B,64] first
    float* attn_out = nullptr;
    if (out_size > B * D_DIM) {
        attn_out = out + (size_t)B * D_DIM;             // [B,1024] second
    }

    sdpa_kernel<<<B, 256>>>(q, k, v, mask, out, attn_out);
}

// round 3
// speedup vs baseline: 1.0054x; 1.0054x over previous
#include <cuda_runtime.h>
#include <cuda_bf16.h>
#include <cstdint>

// Single-query attention, B=4096, T=1024, D=64.
//   attn = softmax(mask_fill(q·k^T / 8, pad_mask, -1000))
//   out  = attn @ v
// Outputs: out [B,64] then attn [B,1024], concatenated (per out_size).
//
// Single-pass ONLINE-softmax formulation: K and V are streamed together in
// one loop (no phase boundary -> no memory-idle bubble), each (warp,half)
// group keeps a running (max, sum, exp-weighted V accumulator) with
// rescaling. Raw masked scores are parked in shared so the attn output is
// recomputed at the end with one expf each — K is never re-read.
//
// pad_mask arrives as a 4-byte dtype (int32 or float32 encoding of bool);
// `!= 0` on the int view is correct for both.

namespace {

constexpr int T_DIM = 1024;
constexpr int D_DIM = 64;
constexpr float INV_TEMP = 0.125f;   // 1/8
constexpr float MASK_FILL = -1000.0f;

__global__ __launch_bounds__(256)
void sdpa_kernel(const float* __restrict__ q,
                 const float* __restrict__ k,
                 const float* __restrict__ v,
                 const int* __restrict__ mask,
                 float* __restrict__ out,
                 float* __restrict__ attn_out)
{
    const int b    = blockIdx.x;
    const int tid  = threadIdx.x;            // 0..255
    const int warp = tid >> 5;               // 0..7
    const int lane = tid & 31;

    __shared__ float4 qs4[D_DIM / 4];        // q row (256 B)
    __shared__ float  sc[T_DIM];             // raw masked scores (4 KB)
    __shared__ float  gm[16];                // per-group running max
    __shared__ float  gl[16];                // per-group running sum
    __shared__ float  outp[8][D_DIM];        // per-warp output partials (2 KB)

    // ---- load q row into shared ----
    if (tid < D_DIM / 4) {
        qs4[tid] = reinterpret_cast<const float4*>(q + (size_t)b * D_DIM)[tid];
    }
    __syncthreads();

    const float4* __restrict__ k4 =
        reinterpret_cast<const float4*>(k + (size_t)b * T_DIM * D_DIM);
    const float4* __restrict__ v4 =
        reinterpret_cast<const float4*>(v + (size_t)b * T_DIM * D_DIM);
    const int* __restrict__ mrow = mask + (size_t)b * T_DIM;

    // Warp layout: 16 lanes per row, 2 rows (halves) per warp-iteration.
    const int half = lane >> 4;              // 0/1: which row of the pair
    const int qi   = lane & 15;              // which float4 within the row
    const float4 qv = qs4[qi];
    const int g = warp * 2 + half;           // group id 0..15

    // ---- fused single pass: scores + online softmax + V accumulation ----
    float  m   = -1e30f;
    float  l   = 0.0f;
    float4 acc = make_float4(0.f, 0.f, 0.f, 0.f);

    #pragma unroll 4
    for (int t = g; t < T_DIM; t += 16) {
        const float4 kv = __ldcs(&k4[t * (D_DIM / 4) + qi]);
        const float4 vv = __ldcs(&v4[t * (D_DIM / 4) + qi]);

        float p = kv.x * qv.x + kv.y * qv.y + kv.z * qv.z + kv.w * qv.w;
        // xor-butterfly over low 4 lane bits: every lane of this half gets
        // the full dot product for its row.
        p += __shfl_xor_sync(0xffffffffu, p, 1);
        p += __shfl_xor_sync(0xffffffffu, p, 2);
        p += __shfl_xor_sync(0xffffffffu, p, 4);
        p += __shfl_xor_sync(0xffffffffu, p, 8);

        float s = p * INV_TEMP;
        if (mrow[t] != 0) s = MASK_FILL;     // broadcast load, same addr/half
        if (qi == 0) sc[t] = s;              // park raw score for attn output

        // online softmax update (replicated across the 16 lanes of the half)
        const float mnew  = fmaxf(m, s);
        const float scale = __expf(m - mnew);    // ==1 when max unchanged
        const float e     = __expf(s - mnew);
        l = l * scale + e;
        acc.x = acc.x * scale + e * vv.x;
        acc.y = acc.y * scale + e * vv.y;
        acc.z = acc.z * scale + e * vv.z;
        acc.w = acc.w * scale + e * vv.w;
        m = mnew;
    }

    if (qi == 0) { gm[g] = m; gl[g] = l; }
    __syncthreads();

    // ---- combine the 16 groups ----
    float M = gm[0];
    #pragma unroll
    for (int i = 1; i < 16; i++) M = fmaxf(M, gm[i]);
    float L = 0.0f;
    #pragma unroll
    for (int i = 0; i < 16; i++) L += gl[i] * __expf(gm[i] - M);
    const float invL = 1.0f / L;

    // rescale this group's accumulator to the global max, fold halves
    const float gs = __expf(m - M);
    acc.x *= gs; acc.y *= gs; acc.z *= gs; acc.w *= gs;
    acc.x += __shfl_xor_sync(0xffffffffu, acc.x, 16);
    acc.y += __shfl_xor_sync(0xffffffffu, acc.y, 16);
    acc.z += __shfl_xor_sync(0xffffffffu, acc.z, 16);
    acc.w += __shfl_xor_sync(0xffffffffu, acc.w, 16);
    if (half == 0) {
        reinterpret_cast<float4*>(outp[warp])[qi] = acc;
    }

    // ---- attn output: p[t] = exp(sc[t]-M)/L (coalesced) ----
    if (attn_out) {
        #pragma unroll
        for (int t = tid; t < T_DIM; t += 256) {
            attn_out[(size_t)b * T_DIM + t] = __expf(sc[t] - M) * invL;
        }
    }
    __syncthreads();

    // ---- final out reduction over warps ----
    if (tid < D_DIM) {
        float s = 0.0f;
        #pragma unroll
        for (int w = 0; w < 8; w++) s += outp[w][tid];
        out[(size_t)b * D_DIM + tid] = s * invL;
    }
}

} // namespace

extern "C" void kernel_launch(void* const* d_in, const int* in_sizes, int n_in,
                              void* d_out, int out_size)
{
    const float* q = (const float*)d_in[0];             // [B,64]
    const float* k = (const float*)d_in[1];             // [B,1024,64]
    const float* v = (const float*)d_in[2];             // [B,1024,64]
    const int*   mask = (const int*)d_in[3];            // [B,1024] bool->4B

    const int B = in_sizes[0] / D_DIM;                  // 4096

    float* out = (float*)d_out;                         // [B,64] first
    float* attn_out = nullptr;
    if (out_size > B * D_DIM) {
        attn_out = out + (size_t)B * D_DIM;             // [B,1024] second
    }

    sdpa_kernel<<<B, 256>>>(q, k, v, mask, out, attn_out);
}

// round 6
// speedup vs baseline: 1.8410x; 1.8312x over previous
#include <cuda_runtime.h>
#include <cuda_bf16.h>
#include <cstdint>

// Single-query attention, B=4096, T=1024, D=64.
//   attn = softmax(mask_fill(q·k^T / 8, pad_mask, -1000))
//   out  = attn @ v
// Outputs: out [B,64] then attn [B,1024], concatenated (per out_size).
//
// KEY OPTIMIZATION: masked positions get score -1000; exp(-1000 - M)
// underflows to exactly 0 in fp32 (same as the fp32 reference), so masked
// K rows AND V rows contribute nothing and are NEVER LOADED. With a
// Bernoulli(1/2) mask this halves the 2.1 GB K/V stream.
//
// Per CTA: compact unmasked row indices (ballot+popc), then run the
// two-phase (QK -> softmax -> PV) pipeline over the compacted list.
//
// DEADLOCK FIX (R5): phase-1 loop trip count must be WARP-UNIFORM because
// the body contains full-mask shuffles. Iterate over pair bases (warp*2,
// step 16); the invalid half loads a safe dummy row and predicates only
// its sc[] store. Phase 3 has no in-loop shuffles, so per-half bounds are
// fine there.
//
// outp/qs4 carry __align__(16): accessed via float4* (R4's crash).

namespace {

constexpr int T_DIM = 1024;
constexpr int D_DIM = 64;
constexpr float INV_TEMP = 0.125f;   // 1/8
constexpr float MASK_FILL = -1000.0f;

__global__ __launch_bounds__(256, 8)
void sdpa_kernel(const float* __restrict__ q,
                 const float* __restrict__ k,
                 const float* __restrict__ v,
                 const int* __restrict__ mask,
                 float* __restrict__ out,
                 float* __restrict__ attn_out)
{
    const int b    = blockIdx.x;
    const int tid  = threadIdx.x;            // 0..255
    const int warp = tid >> 5;               // 0..7
    const int lane = tid & 31;

    __shared__ __align__(16) float4 qs4[D_DIM / 4];   // q row (256 B)
    __shared__ float  sc[T_DIM];             // scores -> probs (4 KB)
    __shared__ int    sh_idx[T_DIM];         // compacted active rows (4 KB)
    __shared__ int    sh_cnt;
    __shared__ float  red_max[8];
    __shared__ float  red_sum[8];
    __shared__ __align__(16) float outp[8][D_DIM];    // per-warp partials (2 KB)

    if (tid < D_DIM / 4) {
        qs4[tid] = reinterpret_cast<const float4*>(q + (size_t)b * D_DIM)[tid];
    }
    if (tid == 0) sh_cnt = 0;
    __syncthreads();

    const float4* __restrict__ k4 =
        reinterpret_cast<const float4*>(k + (size_t)b * T_DIM * D_DIM);
    const float4* __restrict__ v4 =
        reinterpret_cast<const float4*>(v + (size_t)b * T_DIM * D_DIM);
    const int* __restrict__ mrow = mask + (size_t)b * T_DIM;

    // ---- phase 0: prefill scores with MASK_FILL + compact unmasked rows ----
    #pragma unroll
    for (int base = warp * 128; base < warp * 128 + 128; base += 32) {
        const int t = base + lane;
        sc[t] = MASK_FILL;                           // default (masked) score
        const bool act = (mrow[t] == 0);
        const unsigned bal = __ballot_sync(0xffffffffu, act);
        int pos;
        if (lane == 0) pos = atomicAdd(&sh_cnt, __popc(bal));
        pos = __shfl_sync(0xffffffffu, pos, 0);
        if (act) {
            sh_idx[pos + __popc(bal & ((1u << lane) - 1u))] = t;
        }
    }
    __syncthreads();

    int nact = sh_cnt;
    const bool all_masked = (nact == 0);             // P ~ 2^-1024; still exact
    if (all_masked) {
        // uniform softmax over all rows: leave sc == MASK_FILL everywhere,
        // visit every V row.
        for (int t = tid; t < T_DIM; t += 256) sh_idx[t] = t;
        nact = T_DIM;
    }
    __syncthreads();

    // Warp layout: 16 lanes per row, 2 rows (halves) per warp-iteration.
    const int half = lane >> 4;
    const int qi   = lane & 15;
    const float4 qv = qs4[qi];

    // ---- phase 1: scores for ACTIVE rows only ----
    // Warp-uniform trip count: loop over pair base i0; invalid half loads
    // a safe dummy row (sh_idx[i0], in-bounds) and suppresses its store.
    if (!all_masked) {
        #pragma unroll 4
        for (int i0 = warp * 2; i0 < nact; i0 += 16) {
            const int  i     = i0 + half;
            const bool valid = (i < nact);
            const int  t     = sh_idx[valid ? i : i0];
            const float4 kv = __ldcs(&k4[t * (D_DIM / 4) + qi]);
            float p = kv.x * qv.x + kv.y * qv.y + kv.z * qv.z + kv.w * qv.w;
            p += __shfl_xor_sync(0xffffffffu, p, 1);
            p += __shfl_xor_sync(0xffffffffu, p, 2);
            p += __shfl_xor_sync(0xffffffffu, p, 4);
            p += __shfl_xor_sync(0xffffffffu, p, 8);
            if (qi == 0 && valid) sc[t] = p * INV_TEMP;
        }
    }
    __syncthreads();

    // ---- phase 2: softmax over all T (masked entries exp-underflow to 0) ----
    float mx = -1e30f;
    #pragma unroll
    for (int t = tid; t < T_DIM; t += 256) mx = fmaxf(mx, sc[t]);
    #pragma unroll
    for (int o = 16; o > 0; o >>= 1)
        mx = fmaxf(mx, __shfl_xor_sync(0xffffffffu, mx, o));
    if (lane == 0) red_max[warp] = mx;
    __syncthreads();

    float bm = red_max[0];
    #pragma unroll
    for (int i = 1; i < 8; i++) bm = fmaxf(bm, red_max[i]);

    float psum = 0.0f;
    #pragma unroll
    for (int t = tid; t < T_DIM; t += 256) {
        const float e = __expf(sc[t] - bm);
        sc[t] = e;
        psum += e;
    }
    #pragma unroll
    for (int o = 16; o > 0; o >>= 1)
        psum += __shfl_xor_sync(0xffffffffu, psum, o);
    if (lane == 0) red_sum[warp] = psum;
    __syncthreads();

    float tot = red_sum[0];
    #pragma unroll
    for (int i = 1; i < 8; i++) tot += red_sum[i];
    const float inv = 1.0f / tot;

    // normalize in shared; emit attn output (coalesced; masked -> exact 0)
    #pragma unroll
    for (int t = tid; t < T_DIM; t += 256) {
        const float pnorm = sc[t] * inv;
        sc[t] = pnorm;
        if (attn_out) attn_out[(size_t)b * T_DIM + t] = pnorm;
    }
    __syncthreads();

    // ---- phase 3: out[d] = sum over ACTIVE rows of p[t] * v[t,d] ----
    // No shuffles inside this loop, so per-half bounds are deadlock-safe.
    const int g = warp * 2 + half;
    float4 acc = make_float4(0.f, 0.f, 0.f, 0.f);
    #pragma unroll 4
    for (int i = g; i < nact; i += 16) {
        const int t = sh_idx[i];
        const float p = sc[t];
        const float4 vv = __ldcs(&v4[t * (D_DIM / 4) + qi]);
        acc.x += p * vv.x;
        acc.y += p * vv.y;
        acc.z += p * vv.z;
        acc.w += p * vv.w;
    }
    acc.x += __shfl_xor_sync(0xffffffffu, acc.x, 16);
    acc.y += __shfl_xor_sync(0xffffffffu, acc.y, 16);
    acc.z += __shfl_xor_sync(0xffffffffu, acc.z, 16);
    acc.w += __shfl_xor_sync(0xffffffffu, acc.w, 16);
    if (half == 0) {
        reinterpret_cast<float4*>(outp[warp])[qi] = acc;
    }
    __syncthreads();

    if (tid < D_DIM) {
        float s = 0.0f;
        #pragma unroll
        for (int w = 0; w < 8; w++) s += outp[w][tid];
        out[(size_t)b * D_DIM + tid] = s;
    }
}

} // namespace

extern "C" void kernel_launch(void* const* d_in, const int* in_sizes, int n_in,
                              void* d_out, int out_size)
{
    const float* q = (const float*)d_in[0];             // [B,64]
    const float* k = (const float*)d_in[1];             // [B,1024,64]
    const float* v = (const float*)d_in[2];             // [B,1024,64]
    const int*   mask = (const int*)d_in[3];            // [B,1024] bool->4B

    const int B = in_sizes[0] / D_DIM;                  // 4096

    float* out = (float*)d_out;                         // [B,64] first
    float* attn_out = nullptr;
    if (out_size > B * D_DIM) {
        attn_out = out + (size_t)B * D_DIM;             // [B,1024] second
    }

    sdpa_kernel<<<B, 256>>>(q, k, v, mask, out, attn_out);
}